// round 2
// baseline (speedup 1.0000x reference)
#include <cuda_runtime.h>
#include <cuda_bf16.h>
#include <cstdint>
#include <math.h>

// Problem constants
#define LL 128
#define BB 512
#define DD 512
#define SS 128
#define LB (LL * BB)   // 65536

// -------- device scratch --------
__device__ __align__(16) float          g_A[SS * SS];        // exp(log-normalized tparams), [i][j]
__device__ __align__(16) float          g_colbias[SS];       // c - 0.5 * sum_d mu^2/var
__device__ __align__(16) float          g_rvar[DD];          // 1/var
__device__ __align__(16) __nv_bfloat16  g_Mv[SS * DD];       // mu/var in bf16, [s][d]
__device__ __align__(16) float          g_density[(size_t)LB * SS]; // 32 MB
__device__ __align__(16) float          g_perb[BB];          // per-batch logsumexp

#define LOG2PI 1.8378770664093453f
#define LOGPI_INIT (-4.852030263919617f)   // -log(128)

// =====================================================================
// Kernel 1: preprocessing (1 block, 512 threads)
// =====================================================================
__global__ void prep_kernel(const float* __restrict__ tparams,
                            const float* __restrict__ means,
                            const float* __restrict__ var) {
    __shared__ float sred[512];
    int t = threadIdx.x;

    float v = var[t];
    g_rvar[t] = 1.0f / v;
    sred[t] = logf(v);
    __syncthreads();
    for (int off = 256; off > 0; off >>= 1) {
        if (t < off) sred[t] += sred[t + off];
        __syncthreads();
    }
    float slv = sred[0];
    float c = -256.0f * LOG2PI - 0.5f * slv;   // D/2 = 256

    int q   = t & 3;      // 0..3
    int grp = t >> 2;     // 0..127

    // col bias: c - 0.5 * sum_d mu[s,d]^2 / var[d]
    {
        float mq = 0.f;
        for (int d = q; d < DD; d += 4) {
            float m = means[grp * DD + d];
            mq += m * m * g_rvar[d];
        }
        mq += __shfl_xor_sync(0xffffffffu, mq, 1);
        mq += __shfl_xor_sync(0xffffffffu, mq, 2);
        if (q == 0) g_colbias[grp] = c - 0.5f * mq;
    }

    // A = exp(tparams - logsumexp(tparams, axis=1))
    {
        float mx = -1e30f;
        for (int jj = q; jj < SS; jj += 4) mx = fmaxf(mx, tparams[grp * SS + jj]);
        mx = fmaxf(mx, __shfl_xor_sync(0xffffffffu, mx, 1));
        mx = fmaxf(mx, __shfl_xor_sync(0xffffffffu, mx, 2));
        float se = 0.f;
        for (int jj = q; jj < SS; jj += 4) se += __expf(tparams[grp * SS + jj] - mx);
        se += __shfl_xor_sync(0xffffffffu, se, 1);
        se += __shfl_xor_sync(0xffffffffu, se, 2);
        float lse = mx + __logf(se);
        for (int jj = q; jj < SS; jj += 4)
            g_A[grp * SS + jj] = __expf(tparams[grp * SS + jj] - lse);
    }

    // Mv = mu / var in bf16
    for (int idx = t; idx < SS * DD; idx += 512) {
        int d = idx & (DD - 1);
        g_Mv[idx] = __float2bfloat16(means[idx] * g_rvar[d]);
    }
}

// =====================================================================
// Kernel 2: fused density GEMM
//   density[lb][s] = bf16mma(X[lb], Mv[s]) - 0.5*sum(x^2/var) + colbias[s]
// Reads fp32 sents directly; converts to bf16 during staging and computes
// the per-row quadratic term on the fly (no separate pass, no bf16 X buffer).
// Block tile 128x128, K chunks of 64, 256 threads / 8 warps.
// =====================================================================
__device__ __forceinline__ void mma_bf16(float& c0, float& c1, float& c2, float& c3,
                                         uint32_t a0, uint32_t a1, uint32_t a2, uint32_t a3,
                                         uint32_t b0, uint32_t b1) {
    asm volatile(
        "mma.sync.aligned.m16n8k16.row.col.f32.bf16.bf16.f32 "
        "{%0,%1,%2,%3}, {%4,%5,%6,%7}, {%8,%9}, {%0,%1,%2,%3};\n"
        : "+f"(c0), "+f"(c1), "+f"(c2), "+f"(c3)
        : "r"(a0), "r"(a1), "r"(a2), "r"(a3), "r"(b0), "r"(b1));
}

#define SMSTRIDE 72  // padded row stride in bf16 elems

__global__ __launch_bounds__(256) void density_kernel(const float* __restrict__ sents) {
    __shared__ __align__(16) __nv_bfloat16 sA[128 * SMSTRIDE];
    __shared__ __align__(16) __nv_bfloat16 sB[128 * SMSTRIDE];
    __shared__ __align__(16) float srv[DD];
    __shared__ float sXQ[128];

    int tid  = threadIdx.x;
    int warp = tid >> 5, lane = tid & 31;
    int g = lane >> 2, tg = lane & 3;
    int mbase = blockIdx.x * 128;

    for (int i = tid; i < DD; i += 256) srv[i] = g_rvar[i];
    if (tid < 128) sXQ[tid] = 0.f;

    float acc[16][4];
#pragma unroll
    for (int n = 0; n < 16; ++n)
#pragma unroll
        for (int k = 0; k < 4; ++k) acc[n][k] = 0.f;

    __syncthreads();

    for (int ko = 0; ko < 8; ++ko) {
        // ---- stage A: 128x64 fp32 -> bf16 + accumulate x^2/var per row ----
        // tile has 128*16 = 2048 float4s; idx: r = idx>>4, c4 = idx&15
#pragma unroll
        for (int k = 0; k < 8; ++k) {
            int idx = tid + k * 256;
            int r = idx >> 4, c4 = idx & 15;
            float4 x = *reinterpret_cast<const float4*>(
                &sents[(size_t)(mbase + r) * DD + ko * 64 + c4 * 4]);
            __nv_bfloat162 p0 = __float22bfloat162_rn(make_float2(x.x, x.y));
            __nv_bfloat162 p1 = __float22bfloat162_rn(make_float2(x.z, x.w));
            uint2 pk;
            pk.x = *reinterpret_cast<uint32_t*>(&p0);
            pk.y = *reinterpret_cast<uint32_t*>(&p1);
            *reinterpret_cast<uint2*>(&sA[r * SMSTRIDE + c4 * 4]) = pk;

            float4 rv = *reinterpret_cast<const float4*>(&srv[ko * 64 + c4 * 4]);
            float s = x.x * x.x * rv.x + x.y * x.y * rv.y
                    + x.z * x.z * rv.z + x.w * x.w * rv.w;
            // lanes (lane&15) share row r: 16-lane butterfly reduce
            s += __shfl_xor_sync(0xffffffffu, s, 1);
            s += __shfl_xor_sync(0xffffffffu, s, 2);
            s += __shfl_xor_sync(0xffffffffu, s, 4);
            s += __shfl_xor_sync(0xffffffffu, s, 8);
            if ((lane & 15) == 0) atomicAdd(&sXQ[r], -0.5f * s);
        }
        // ---- stage B: 128x64 bf16 from g_Mv ----
#pragma unroll
        for (int k = 0; k < 4; ++k) {
            int idx = tid + k * 256;         // 1024 uint4 total
            int r = idx >> 3, c8 = idx & 7;
            uint4 vb = *reinterpret_cast<const uint4*>(&g_Mv[(size_t)r * DD + ko * 64 + c8 * 8]);
            *reinterpret_cast<uint4*>(&sB[r * SMSTRIDE + c8 * 8]) = vb;
        }
        __syncthreads();

#pragma unroll
        for (int ks = 0; ks < 4; ++ks) {
            int k0 = ks * 16 + tg * 2;
            uint32_t a0 = *reinterpret_cast<const uint32_t*>(&sA[(warp * 16 + g)     * SMSTRIDE + k0]);
            uint32_t a1 = *reinterpret_cast<const uint32_t*>(&sA[(warp * 16 + g + 8) * SMSTRIDE + k0]);
            uint32_t a2 = *reinterpret_cast<const uint32_t*>(&sA[(warp * 16 + g)     * SMSTRIDE + k0 + 8]);
            uint32_t a3 = *reinterpret_cast<const uint32_t*>(&sA[(warp * 16 + g + 8) * SMSTRIDE + k0 + 8]);
#pragma unroll
            for (int n = 0; n < 16; ++n) {
                uint32_t b0 = *reinterpret_cast<const uint32_t*>(&sB[(n * 8 + g) * SMSTRIDE + k0]);
                uint32_t b1 = *reinterpret_cast<const uint32_t*>(&sB[(n * 8 + g) * SMSTRIDE + k0 + 8]);
                mma_bf16(acc[n][0], acc[n][1], acc[n][2], acc[n][3], a0, a1, a2, a3, b0, b1);
            }
        }
        __syncthreads();
    }

    int r0l = warp * 16 + g;
    int r1l = r0l + 8;
    int r0 = mbase + r0l, r1 = mbase + r1l;
    float xq0 = sXQ[r0l], xq1 = sXQ[r1l];
#pragma unroll
    for (int n = 0; n < 16; ++n) {
        int col = n * 8 + tg * 2;
        float cb0 = g_colbias[col], cb1 = g_colbias[col + 1];
        g_density[(size_t)r0 * SS + col]     = acc[n][0] + xq0 + cb0;
        g_density[(size_t)r0 * SS + col + 1] = acc[n][1] + xq0 + cb1;
        g_density[(size_t)r1 * SS + col]     = acc[n][2] + xq1 + cb0;
        g_density[(size_t)r1 * SS + col + 1] = acc[n][3] + xq1 + cb1;
    }
}

// =====================================================================
// Kernel 3: forward recurrence.
// 128 blocks (one per SM, balanced wave), 128 threads, 4 batches/thread.
// A (64 KB fp32) resident in smem; 4 FMAs per A-load -> FFMA-issue bound.
// =====================================================================
#define RECUR_SMEM ((16384 + 512 + 512 + 16) * 4)

__device__ __forceinline__ float4 max4(float4 a, float4 b) {
    return make_float4(fmaxf(a.x, b.x), fmaxf(a.y, b.y), fmaxf(a.z, b.z), fmaxf(a.w, b.w));
}

__global__ __launch_bounds__(128) void recur_kernel(const float* __restrict__ masks) {
    extern __shared__ float sh[];
    float*  shA    = sh;                                    // 16384 floats (64 KB)
    float4* sp4    = reinterpret_cast<float4*>(sh + 16384); // 128 float4
    float4* smask4 = reinterpret_cast<float4*>(sh + 16896); // 128 float4
    float4* sm4    = reinterpret_cast<float4*>(sh + 17408); // 4 float4

    int j = threadIdx.x;
    int warp = j >> 5, lane = j & 31;
    int b0 = blockIdx.x * 4;

    for (int i = j; i < SS * SS; i += 128) shA[i] = g_A[i];
    smask4[j] = *reinterpret_cast<const float4*>(&masks[j * BB + b0]);

    float4 al;
    al.x = LOGPI_INIT + g_density[(size_t)(b0 + 0) * SS + j];
    al.y = LOGPI_INIT + g_density[(size_t)(b0 + 1) * SS + j];
    al.z = LOGPI_INIT + g_density[(size_t)(b0 + 2) * SS + j];
    al.w = LOGPI_INIT + g_density[(size_t)(b0 + 3) * SS + j];
    __syncthreads();

    for (int l = 1; l < LL; ++l) {
        // exact block max per batch: warp shfl tree + 4-entry smem combine
        float4 w = al;
#pragma unroll
        for (int off = 16; off > 0; off >>= 1) {
            float4 o;
            o.x = __shfl_xor_sync(0xffffffffu, w.x, off);
            o.y = __shfl_xor_sync(0xffffffffu, w.y, off);
            o.z = __shfl_xor_sync(0xffffffffu, w.z, off);
            o.w = __shfl_xor_sync(0xffffffffu, w.w, off);
            w = max4(w, o);
        }
        if (lane == 0) sm4[warp] = w;
        __syncthreads();
        float4 m = max4(max4(sm4[0], sm4[1]), max4(sm4[2], sm4[3]));

        float4 p;
        p.x = __expf(al.x - m.x);
        p.y = __expf(al.y - m.y);
        p.z = __expf(al.z - m.z);
        p.w = __expf(al.w - m.w);
        sp4[j] = p;

        // prefetch density rows for this step (L2-resident; hidden behind matvec)
        size_t base = (size_t)l * BB * SS;
        float4 d;
        d.x = g_density[base + (size_t)(b0 + 0) * SS + j];
        d.y = g_density[base + (size_t)(b0 + 1) * SS + j];
        d.z = g_density[base + (size_t)(b0 + 2) * SS + j];
        d.w = g_density[base + (size_t)(b0 + 3) * SS + j];
        float4 mk = smask4[l];
        __syncthreads();

        float4 acc = make_float4(0.f, 0.f, 0.f, 0.f);
#pragma unroll 8
        for (int i = 0; i < SS; ++i) {
            float  a  = shA[i * SS + j];
            float4 pv = sp4[i];
            acc.x = fmaf(pv.x, a, acc.x);
            acc.y = fmaf(pv.y, a, acc.y);
            acc.z = fmaf(pv.z, a, acc.z);
            acc.w = fmaf(pv.w, a, acc.w);
        }

        float4 na;
        na.x = d.x + m.x + __logf(acc.x);
        na.y = d.y + m.y + __logf(acc.y);
        na.z = d.z + m.z + __logf(acc.z);
        na.w = d.w + m.w + __logf(acc.w);
        al.x = mk.x * na.x + (1.f - mk.x) * al.x;
        al.y = mk.y * na.y + (1.f - mk.y) * al.y;
        al.z = mk.z * na.z + (1.f - mk.z) * al.z;
        al.w = mk.w * na.w + (1.f - mk.w) * al.w;
    }

    // final per-batch logsumexp over the 128 states
    float4 w = al;
#pragma unroll
    for (int off = 16; off > 0; off >>= 1) {
        float4 o;
        o.x = __shfl_xor_sync(0xffffffffu, w.x, off);
        o.y = __shfl_xor_sync(0xffffffffu, w.y, off);
        o.z = __shfl_xor_sync(0xffffffffu, w.z, off);
        o.w = __shfl_xor_sync(0xffffffffu, w.w, off);
        w = max4(w, o);
    }
    if (lane == 0) sm4[warp] = w;
    __syncthreads();
    float4 m = max4(max4(sm4[0], sm4[1]), max4(sm4[2], sm4[3]));

    float4 e;
    e.x = __expf(al.x - m.x);
    e.y = __expf(al.y - m.y);
    e.z = __expf(al.z - m.z);
    e.w = __expf(al.w - m.w);
#pragma unroll
    for (int off = 16; off > 0; off >>= 1) {
        e.x += __shfl_xor_sync(0xffffffffu, e.x, off);
        e.y += __shfl_xor_sync(0xffffffffu, e.y, off);
        e.z += __shfl_xor_sync(0xffffffffu, e.z, off);
        e.w += __shfl_xor_sync(0xffffffffu, e.w, off);
    }
    __syncthreads();   // sm4 reads done before reuse
    if (lane == 0) sp4[warp] = e;   // reuse sp4 as scratch
    __syncthreads();
    if (j == 0) {
        float4 s0 = sp4[0], s1 = sp4[1], s2 = sp4[2], s3 = sp4[3];
        float4 r;
        r.x = m.x + __logf(s0.x + s1.x + s2.x + s3.x);
        r.y = m.y + __logf(s0.y + s1.y + s2.y + s3.y);
        r.z = m.z + __logf(s0.z + s1.z + s2.z + s3.z);
        r.w = m.w + __logf(s0.w + s1.w + s2.w + s3.w);
        *reinterpret_cast<float4*>(&g_perb[b0]) = r;
    }
}

// =====================================================================
// Kernel 4: deterministic final reduction over 512 batch rows
// =====================================================================
__global__ void finalize_kernel(float* __restrict__ out, int out_size) {
    __shared__ float s[256];
    int t = threadIdx.x;
    s[t] = g_perb[t] + g_perb[t + 256];
    __syncthreads();
    for (int off = 128; off > 0; off >>= 1) {
        if (t < off) s[t] += s[t + off];
        __syncthreads();
    }
    for (int i = t; i < out_size; i += 256)
        if (i != 0) out[i] = 0.f;   // jacobian_loss = 0
    if (t == 0) out[0] = s[0];
}

// =====================================================================
extern "C" void kernel_launch(void* const* d_in, const int* in_sizes, int n_in,
                              void* d_out, int out_size) {
    const float* sents   = (const float*)d_in[0];
    const float* masks   = (const float*)d_in[1];
    const float* tparams = (const float*)d_in[2];
    const float* means   = (const float*)d_in[3];
    const float* var     = (const float*)d_in[4];
    float* out = (float*)d_out;

    cudaFuncSetAttribute(recur_kernel, cudaFuncAttributeMaxDynamicSharedMemorySize, RECUR_SMEM);

    prep_kernel<<<1, 512>>>(tparams, means, var);
    density_kernel<<<LB / 128, 256>>>(sents);
    recur_kernel<<<BB / 4, 128, RECUR_SMEM>>>(masks);
    finalize_kernel<<<1, 256>>>(out, out_size);
}

// round 3
// speedup vs baseline: 1.3813x; 1.3813x over previous
#include <cuda_runtime.h>
#include <cuda_bf16.h>
#include <cstdint>
#include <math.h>

// Problem constants
#define LL 128
#define BB 512
#define DD 512
#define SS 128
#define LB (LL * BB)   // 65536

// -------- device scratch --------
__device__ __align__(16) float          g_A[SS * SS];        // exp(log-normalized tparams), [i][j]
__device__ __align__(16) float          g_colbias[SS];       // c - 0.5 * sum_d mu^2/var
__device__ __align__(16) float          g_rvar[DD];          // 1/var
__device__ __align__(16) __nv_bfloat16  g_Mv[SS * DD];       // mu/var in bf16, [s][d]
__device__ __align__(16) __nv_bfloat16  g_E[(size_t)LB * SS];    // exp(d - rowmax), bf16, 16 MB
__device__ __align__(16) float          g_dmax[LB];          // per-row max (incl xq), [L][B]
__device__ __align__(16) float          g_perb[BB];          // per-batch logsumexp

#define LOG2PI 1.8378770664093453f
#define LOGPI_INIT (-4.852030263919617f)   // -log(128)

// ---- fast exp on the FMA pipe (x <= 0 expected; flushes below -80) ----
__device__ __forceinline__ float fexp(float x) {
    float t = fmaf(x, 1.4426950408889634f, 12582912.0f);   // round-to-int magic
    int   ni = __float_as_int(t) - 0x4B400000;             // integer n
    float n  = t - 12582912.0f;
    float f  = fmaf(x, 1.4426950408889634f, -n);           // f in [-0.5, 0.5]
    float r  = 0.0013333558f;
    r = fmaf(r, f, 0.0096181291f);
    r = fmaf(r, f, 0.0555041087f);
    r = fmaf(r, f, 0.2402264689f);
    r = fmaf(r, f, 0.6931471806f);
    r = fmaf(r, f, 1.0f);
    float res = __int_as_float(__float_as_int(r) + (ni << 23));
    return (x > -80.0f) ? res : 0.0f;
}

__device__ __forceinline__ uint32_t pk(__nv_bfloat162 v) { return *reinterpret_cast<uint32_t*>(&v); }
__device__ __forceinline__ __nv_bfloat162 upk(uint32_t v) { return *reinterpret_cast<__nv_bfloat162*>(&v); }

// =====================================================================
// Kernel 1: preprocessing (1 block, 512 threads)
// =====================================================================
__global__ void prep_kernel(const float* __restrict__ tparams,
                            const float* __restrict__ means,
                            const float* __restrict__ var) {
    __shared__ float sred[512];
    int t = threadIdx.x;

    float v = var[t];
    g_rvar[t] = 1.0f / v;
    sred[t] = logf(v);
    __syncthreads();
    for (int off = 256; off > 0; off >>= 1) {
        if (t < off) sred[t] += sred[t + off];
        __syncthreads();
    }
    float slv = sred[0];
    float c = -256.0f * LOG2PI - 0.5f * slv;   // D/2 = 256

    int q   = t & 3;      // 0..3
    int grp = t >> 2;     // 0..127

    // col bias: c - 0.5 * sum_d mu[s,d]^2 / var[d]
    {
        float mq = 0.f;
        for (int d = q; d < DD; d += 4) {
            float m = means[grp * DD + d];
            mq += m * m * g_rvar[d];
        }
        mq += __shfl_xor_sync(0xffffffffu, mq, 1);
        mq += __shfl_xor_sync(0xffffffffu, mq, 2);
        if (q == 0) g_colbias[grp] = c - 0.5f * mq;
    }

    // A = exp(tparams - logsumexp(tparams, axis=1))
    {
        float mx = -1e30f;
        for (int jj = q; jj < SS; jj += 4) mx = fmaxf(mx, tparams[grp * SS + jj]);
        mx = fmaxf(mx, __shfl_xor_sync(0xffffffffu, mx, 1));
        mx = fmaxf(mx, __shfl_xor_sync(0xffffffffu, mx, 2));
        float se = 0.f;
        for (int jj = q; jj < SS; jj += 4) se += __expf(tparams[grp * SS + jj] - mx);
        se += __shfl_xor_sync(0xffffffffu, se, 1);
        se += __shfl_xor_sync(0xffffffffu, se, 2);
        float lse = mx + __logf(se);
        for (int jj = q; jj < SS; jj += 4)
            g_A[grp * SS + jj] = __expf(tparams[grp * SS + jj] - lse);
    }

    // Mv = mu / var in bf16
    for (int idx = t; idx < SS * DD; idx += 512) {
        int d = idx & (DD - 1);
        g_Mv[idx] = __float2bfloat16(means[idx] * g_rvar[d]);
    }
}

// =====================================================================
// Kernel 2: fused density GEMM -> E = exp(d - rowmax) in bf16, dmax fp32
//   d[lb][s] = bf16mma(X[lb], Mv[s]) - 0.5*sum(x^2/var) + colbias[s]
// Block tile 128x128, K chunks of 64, 256 threads / 8 warps.
// =====================================================================
__device__ __forceinline__ void mma_bf16(float& c0, float& c1, float& c2, float& c3,
                                         uint32_t a0, uint32_t a1, uint32_t a2, uint32_t a3,
                                         uint32_t b0, uint32_t b1) {
    asm volatile(
        "mma.sync.aligned.m16n8k16.row.col.f32.bf16.bf16.f32 "
        "{%0,%1,%2,%3}, {%4,%5,%6,%7}, {%8,%9}, {%0,%1,%2,%3};\n"
        : "+f"(c0), "+f"(c1), "+f"(c2), "+f"(c3)
        : "r"(a0), "r"(a1), "r"(a2), "r"(a3), "r"(b0), "r"(b1));
}

#define SMSTRIDE 72  // padded row stride in bf16 elems

__global__ __launch_bounds__(256) void density_kernel(const float* __restrict__ sents) {
    __shared__ __align__(16) __nv_bfloat16 sA[128 * SMSTRIDE];
    __shared__ __align__(16) __nv_bfloat16 sB[128 * SMSTRIDE];
    __shared__ __align__(16) float srv[DD];
    __shared__ float sXQ[128];
    __shared__ float scb[128];

    int tid  = threadIdx.x;
    int warp = tid >> 5, lane = tid & 31;
    int g = lane >> 2, tg = lane & 3;
    int mbase = blockIdx.x * 128;

    for (int i = tid; i < DD; i += 256) srv[i] = g_rvar[i];
    if (tid < 128) scb[tid] = g_colbias[tid];

    float acc[16][4];
#pragma unroll
    for (int n = 0; n < 16; ++n)
#pragma unroll
        for (int k = 0; k < 4; ++k) acc[n][k] = 0.f;

    float xqp[8];
#pragma unroll
    for (int k = 0; k < 8; ++k) xqp[k] = 0.f;

    __syncthreads();

    for (int ko = 0; ko < 8; ++ko) {
        // ---- stage A: 128x64 fp32 -> bf16 + per-thread x^2/var partials ----
#pragma unroll
        for (int k = 0; k < 8; ++k) {
            int idx = tid + k * 256;
            int r = idx >> 4, c4 = idx & 15;
            float4 x = *reinterpret_cast<const float4*>(
                &sents[(size_t)(mbase + r) * DD + ko * 64 + c4 * 4]);
            __nv_bfloat162 p0 = __float22bfloat162_rn(make_float2(x.x, x.y));
            __nv_bfloat162 p1 = __float22bfloat162_rn(make_float2(x.z, x.w));
            uint2 pkk;
            pkk.x = pk(p0);
            pkk.y = pk(p1);
            *reinterpret_cast<uint2*>(&sA[r * SMSTRIDE + c4 * 4]) = pkk;

            float4 rv = *reinterpret_cast<const float4*>(&srv[ko * 64 + c4 * 4]);
            xqp[k] += x.x * x.x * rv.x + x.y * x.y * rv.y
                    + x.z * x.z * rv.z + x.w * x.w * rv.w;
        }
        // ---- stage B: 128x64 bf16 from g_Mv ----
#pragma unroll
        for (int k = 0; k < 4; ++k) {
            int idx = tid + k * 256;         // 1024 uint4 total
            int r = idx >> 3, c8 = idx & 7;
            uint4 vb = *reinterpret_cast<const uint4*>(&g_Mv[(size_t)r * DD + ko * 64 + c8 * 8]);
            *reinterpret_cast<uint4*>(&sB[r * SMSTRIDE + c8 * 8]) = vb;
        }
        __syncthreads();

#pragma unroll
        for (int ks = 0; ks < 4; ++ks) {
            int k0 = ks * 16 + tg * 2;
            uint32_t a0 = *reinterpret_cast<const uint32_t*>(&sA[(warp * 16 + g)     * SMSTRIDE + k0]);
            uint32_t a1 = *reinterpret_cast<const uint32_t*>(&sA[(warp * 16 + g + 8) * SMSTRIDE + k0]);
            uint32_t a2 = *reinterpret_cast<const uint32_t*>(&sA[(warp * 16 + g)     * SMSTRIDE + k0 + 8]);
            uint32_t a3 = *reinterpret_cast<const uint32_t*>(&sA[(warp * 16 + g + 8) * SMSTRIDE + k0 + 8]);
#pragma unroll
            for (int n = 0; n < 16; ++n) {
                uint32_t b0 = *reinterpret_cast<const uint32_t*>(&sB[(n * 8 + g) * SMSTRIDE + k0]);
                uint32_t b1 = *reinterpret_cast<const uint32_t*>(&sB[(n * 8 + g) * SMSTRIDE + k0 + 8]);
                mma_bf16(acc[n][0], acc[n][1], acc[n][2], acc[n][3], a0, a1, a2, a3, b0, b1);
            }
        }
        __syncthreads();
    }

    // xq: reduce 16-lane groups (lanes sharing a row differ only in c4)
#pragma unroll
    for (int k = 0; k < 8; ++k) {
        float s = xqp[k];
        s += __shfl_xor_sync(0xffffffffu, s, 1);
        s += __shfl_xor_sync(0xffffffffu, s, 2);
        s += __shfl_xor_sync(0xffffffffu, s, 4);
        s += __shfl_xor_sync(0xffffffffu, s, 8);
        if ((lane & 15) == 0) sXQ[(tid >> 4) + k * 16] = -0.5f * s;
    }
    __syncthreads();

    int r0l = warp * 16 + g;
    int r1l = r0l + 8;
    int r0 = mbase + r0l, r1 = mbase + r1l;
    float xq0 = sXQ[r0l], xq1 = sXQ[r1l];

    // add colbias, find row maxes (4 lanes per row: shfl over tg bits)
    float mx0 = -1e30f, mx1 = -1e30f;
#pragma unroll
    for (int n = 0; n < 16; ++n) {
        int col = n * 8 + tg * 2;
        float cb0 = scb[col], cb1 = scb[col + 1];
        acc[n][0] += cb0; acc[n][1] += cb1;
        acc[n][2] += cb0; acc[n][3] += cb1;
        mx0 = fmaxf(mx0, fmaxf(acc[n][0], acc[n][1]));
        mx1 = fmaxf(mx1, fmaxf(acc[n][2], acc[n][3]));
    }
    mx0 = fmaxf(mx0, __shfl_xor_sync(0xffffffffu, mx0, 1));
    mx0 = fmaxf(mx0, __shfl_xor_sync(0xffffffffu, mx0, 2));
    mx1 = fmaxf(mx1, __shfl_xor_sync(0xffffffffu, mx1, 1));
    mx1 = fmaxf(mx1, __shfl_xor_sync(0xffffffffu, mx1, 2));

#pragma unroll
    for (int n = 0; n < 16; ++n) {
        int col = n * 8 + tg * 2;
        __nv_bfloat162 e01 = __floats2bfloat162_rn(fexp(acc[n][0] - mx0), fexp(acc[n][1] - mx0));
        __nv_bfloat162 e23 = __floats2bfloat162_rn(fexp(acc[n][2] - mx1), fexp(acc[n][3] - mx1));
        *reinterpret_cast<uint32_t*>(&g_E[(size_t)r0 * SS + col]) = pk(e01);
        *reinterpret_cast<uint32_t*>(&g_E[(size_t)r1 * SS + col]) = pk(e23);
    }
    if (tg == 0) {
        g_dmax[r0] = mx0 + xq0;
        g_dmax[r1] = mx1 + xq1;
    }
}

// =====================================================================
// Kernel 3: forward recurrence (offset-tracked, bf16x2 matvec, A in regs)
// 128 CTAs x 256 threads. thread = (j, half); half owns i in [half*64, +64).
// p' = E .* (p @ A); M += dmax. Renorm max->1 every 8 steps.
// =====================================================================
__global__ __launch_bounds__(256) void recur_kernel(const float* __restrict__ masks) {
    __shared__ uint2  sp[2][128];     // p: (bf16x2 b01, bf16x2 b23) per j, ping-pong
    __shared__ uint2  spart[2][128];  // per-half partial acc
    __shared__ float4 sdmax[128];     // dmax[l][b0..3]
    __shared__ float4 smask[128];     // masks[l][b0..3]
    __shared__ float4 sredm[8];

    int tid  = threadIdx.x;
    int j    = tid & 127, half = tid >> 7;
    int warp = tid >> 5, lane = tid & 31;
    int b0   = blockIdx.x * 4;

    // A column j, own i-range, as duplicated bf16x2
    __nv_bfloat162 areg[64];
#pragma unroll
    for (int i = 0; i < 64; ++i)
        areg[i] = __float2bfloat162_rn(g_A[(half * 64 + i) * SS + j]);

    if (half == 0) sdmax[j] = *reinterpret_cast<const float4*>(&g_dmax[j * BB + b0]);
    else           smask[j] = *reinterpret_cast<const float4*>(&masks[j * BB + b0]);

    // init: p = E[0], M = -log S + dmax0
    const __nv_bfloat16* Eb = g_E + (size_t)b0 * SS + j;
    __nv_bfloat162 pn01 = __floats2bfloat162_rn(__bfloat162float(Eb[0]),
                                                __bfloat162float(Eb[SS]));
    __nv_bfloat162 pn23 = __floats2bfloat162_rn(__bfloat162float(Eb[2 * SS]),
                                                __bfloat162float(Eb[3 * SS]));
    if (half == 0) { sp[0][j].x = pk(pn01); sp[0][j].y = pk(pn23); }
    __syncthreads();

    float4 dm0 = sdmax[0];
    float4 M4 = make_float4(LOGPI_INIT + dm0.x, LOGPI_INIT + dm0.y,
                            LOGPI_INIT + dm0.z, LOGPI_INIT + dm0.w);

    int cur = 0;
    for (int l = 1; l < LL; ++l) {
        // prefetch E (independent of matvec)
        const __nv_bfloat16* Ep = g_E + ((size_t)l * BB + b0) * SS + j;
        float e0 = __bfloat162float(Ep[0]);
        float e1 = __bfloat162float(Ep[SS]);
        float e2 = __bfloat162float(Ep[2 * SS]);
        float e3 = __bfloat162float(Ep[3 * SS]);

        // partial matvec over own 64 i (A in regs, p broadcast from smem)
        __nv_bfloat162 acc01 = __floats2bfloat162_rn(0.f, 0.f);
        __nv_bfloat162 acc23 = acc01;
#pragma unroll
        for (int i = 0; i < 64; ++i) {
            uint2 pv = sp[cur][half * 64 + i];
            acc01 = __hfma2(areg[i], upk(pv.x), acc01);
            acc23 = __hfma2(areg[i], upk(pv.y), acc23);
        }
        spart[half][j].x = pk(acc01);
        spart[half][j].y = pk(acc23);
        __syncthreads();                    // BAR1
        uint2 o = spart[1 - half][j];
        acc01 = __hadd2(acc01, upk(o.x));
        acc23 = __hadd2(acc23, upk(o.y));

        // p' = E * acc (fp32 intermediate for the multiply precision)
        float a0 = __bfloat162float(__low2bfloat16(acc01)) * e0;
        float a1 = __bfloat162float(__high2bfloat16(acc01)) * e1;
        float a2 = __bfloat162float(__low2bfloat16(acc23)) * e2;
        float a3 = __bfloat162float(__high2bfloat16(acc23)) * e3;

        // binary mask blend + M advance
        float4 mk = smask[l];
        float4 dm = sdmax[l];
        float s0 = (mk.x >= 0.5f) ? 1.f : 0.f;
        float s1 = (mk.y >= 0.5f) ? 1.f : 0.f;
        float s2 = (mk.z >= 0.5f) ? 1.f : 0.f;
        float s3 = (mk.w >= 0.5f) ? 1.f : 0.f;
        float p0 = __bfloat162float(__low2bfloat16(pn01));
        float p1 = __bfloat162float(__high2bfloat16(pn01));
        float p2 = __bfloat162float(__low2bfloat16(pn23));
        float p3 = __bfloat162float(__high2bfloat16(pn23));
        a0 = s0 * a0 + (1.f - s0) * p0;  M4.x += s0 * dm.x;
        a1 = s1 * a1 + (1.f - s1) * p1;  M4.y += s1 * dm.y;
        a2 = s2 * a2 + (1.f - s2) * p2;  M4.z += s2 * dm.z;
        a3 = s3 * a3 + (1.f - s3) * p3;  M4.w += s3 * dm.w;

        // renorm every 8 steps: fold block max into M
        if ((l & 7) == 0) {
            float4 mv = make_float4(a0, a1, a2, a3);
#pragma unroll
            for (int off = 16; off > 0; off >>= 1) {
                mv.x = fmaxf(mv.x, __shfl_xor_sync(0xffffffffu, mv.x, off));
                mv.y = fmaxf(mv.y, __shfl_xor_sync(0xffffffffu, mv.y, off));
                mv.z = fmaxf(mv.z, __shfl_xor_sync(0xffffffffu, mv.z, off));
                mv.w = fmaxf(mv.w, __shfl_xor_sync(0xffffffffu, mv.w, off));
            }
            if (lane == 0) sredm[warp] = mv;
            __syncthreads();
            mv = sredm[0];
#pragma unroll
            for (int w = 1; w < 8; ++w) {
                float4 t = sredm[w];
                mv.x = fmaxf(mv.x, t.x); mv.y = fmaxf(mv.y, t.y);
                mv.z = fmaxf(mv.z, t.z); mv.w = fmaxf(mv.w, t.w);
            }
            mv.x = fmaxf(mv.x, 1e-30f); mv.y = fmaxf(mv.y, 1e-30f);
            mv.z = fmaxf(mv.z, 1e-30f); mv.w = fmaxf(mv.w, 1e-30f);
            a0 /= mv.x; a1 /= mv.y; a2 /= mv.z; a3 /= mv.w;
            M4.x += __logf(mv.x); M4.y += __logf(mv.y);
            M4.z += __logf(mv.z); M4.w += __logf(mv.w);
        }

        pn01 = __floats2bfloat162_rn(a0, a1);
        pn23 = __floats2bfloat162_rn(a2, a3);
        int nxt = cur ^ 1;
        if (half == 0) { sp[nxt][j].x = pk(pn01); sp[nxt][j].y = pk(pn23); }
        __syncthreads();                    // BAR2
        cur = nxt;
    }

    // objective per batch: M + log(sum_j p_j)   (half 0 covers each j once)
    float f0 = __bfloat162float(__low2bfloat16(pn01));
    float f1 = __bfloat162float(__high2bfloat16(pn01));
    float f2 = __bfloat162float(__low2bfloat16(pn23));
    float f3 = __bfloat162float(__high2bfloat16(pn23));
#pragma unroll
    for (int off = 16; off > 0; off >>= 1) {
        f0 += __shfl_xor_sync(0xffffffffu, f0, off);
        f1 += __shfl_xor_sync(0xffffffffu, f1, off);
        f2 += __shfl_xor_sync(0xffffffffu, f2, off);
        f3 += __shfl_xor_sync(0xffffffffu, f3, off);
    }
    if (half == 0 && lane == 0) sredm[warp] = make_float4(f0, f1, f2, f3);
    __syncthreads();
    if (tid == 0) {
        float4 S = sredm[0];
#pragma unroll
        for (int w = 1; w < 4; ++w) {
            float4 t = sredm[w];
            S.x += t.x; S.y += t.y; S.z += t.z; S.w += t.w;
        }
        float4 r;
        r.x = M4.x + __logf(S.x);
        r.y = M4.y + __logf(S.y);
        r.z = M4.z + __logf(S.z);
        r.w = M4.w + __logf(S.w);
        *reinterpret_cast<float4*>(&g_perb[b0]) = r;
    }
}

// =====================================================================
// Kernel 4: deterministic final reduction over 512 batch rows
// =====================================================================
__global__ void finalize_kernel(float* __restrict__ out, int out_size) {
    __shared__ float s[256];
    int t = threadIdx.x;
    s[t] = g_perb[t] + g_perb[t + 256];
    __syncthreads();
    for (int off = 128; off > 0; off >>= 1) {
        if (t < off) s[t] += s[t + off];
        __syncthreads();
    }
    for (int i = t; i < out_size; i += 256)
        if (i != 0) out[i] = 0.f;   // jacobian_loss = 0
    if (t == 0) out[0] = s[0];
}

// =====================================================================
extern "C" void kernel_launch(void* const* d_in, const int* in_sizes, int n_in,
                              void* d_out, int out_size) {
    const float* sents   = (const float*)d_in[0];
    const float* masks   = (const float*)d_in[1];
    const float* tparams = (const float*)d_in[2];
    const float* means   = (const float*)d_in[3];
    const float* var     = (const float*)d_in[4];
    float* out = (float*)d_out;

    prep_kernel<<<1, 512>>>(tparams, means, var);
    density_kernel<<<LB / 128, 256>>>(sents);
    recur_kernel<<<BB / 4, 256>>>(masks);
    finalize_kernel<<<1, 256>>>(out, out_size);
}